// round 3
// baseline (speedup 1.0000x reference)
#include <cuda_runtime.h>
#include <cstdint>

#define E_EDGES 16384
#define NN      10000
#define D       128

// ---------------- scratch (device globals; no allocation allowed) ----------
__device__ float g_h[E_EDGES * D];     // relu(edge_attr @ w1 + b1)
__device__ float g_sum[NN * D];        // segment sums
__device__ float g_cnt[NN];            // segment counts
__device__ int   g_src[E_EDGES];       // canonical int32 src indices
__device__ int   g_dst[E_EDGES];       // canonical int32 dst indices
__device__ int   g_is64;               // 1 if edge_index buffer is int64

// ---------------- kernel A: detect edge_index dtype -------------------------
// If the buffer is int64, every odd 32-bit word of the first row is the high
// half of a value in [0,10000) -> zero. If int32, odd words are live indices.
__global__ void __launch_bounds__(256) k_detect(const unsigned* __restrict__ a) {
    __shared__ unsigned red[256];
    unsigned acc = 0;
    for (int i = threadIdx.x; i < E_EDGES; i += 256)
        acc |= a[2 * i + 1];
    red[threadIdx.x] = acc;
    __syncthreads();
    for (int s = 128; s > 0; s >>= 1) {
        if (threadIdx.x < s) red[threadIdx.x] |= red[threadIdx.x + s];
        __syncthreads();
    }
    if (threadIdx.x == 0) g_is64 = (red[0] == 0) ? 1 : 0;
}

// ---------------- kernel B: canonicalize indices to clamped int32 ----------
__global__ void __launch_bounds__(256) k_convert(const void* __restrict__ ebuf) {
    const int i = blockIdx.x * blockDim.x + threadIdx.x;
    if (i >= E_EDGES) return;
    int s, d;
    if (g_is64) {
        const long long* a64 = (const long long*)ebuf;
        s = (int)a64[i];
        d = (int)a64[E_EDGES + i];
    } else {
        const int* a32 = (const int*)ebuf;
        s = a32[i];
        d = a32[E_EDGES + i];
    }
    s = min(max(s, 0), NN - 1);
    d = min(max(d, 0), NN - 1);
    g_src[i] = s;
    g_dst[i] = d;
}

// ---------------- kernel 0: zero scratch -----------------------------------
__global__ void k_zero() {
    int i = blockIdx.x * blockDim.x + threadIdx.x;
    if (i < NN * D) g_sum[i] = 0.0f;
    if (i < NN)     g_cnt[i] = 0.0f;
}

// ---------------- kernel 1: h = relu(edge_attr @ w1 + b1) ------------------
__global__ void __launch_bounds__(128) k_edge_mlp1(
        const float* __restrict__ ea,
        const float* __restrict__ w1,
        const float* __restrict__ b1) {
    __shared__ float s[32 * D];
    const int e0 = blockIdx.x * 32;
    const int c  = threadIdx.x;

    for (int idx = c; idx < 32 * D; idx += 128)
        s[idx] = ea[(size_t)e0 * D + idx];
    __syncthreads();

    float acc[32];
    const float bc = b1[c];
#pragma unroll
    for (int e = 0; e < 32; e++) acc[e] = bc;

    for (int k = 0; k < D; k++) {
        const float w = w1[k * D + c];
#pragma unroll
        for (int e = 0; e < 32; e++) acc[e] += s[e * D + k] * w;
    }
#pragma unroll
    for (int e = 0; e < 32; e++)
        g_h[(size_t)(e0 + e) * D + c] = fmaxf(acc[e], 0.0f);
}

// ---------------- kernel 2: fused bilinear msg + scatter -------------------
// msg[e,o] = sum_{k,i} h[e,k] * x[src_e,i] * w2[k, i*D+o]  (+ b2 as k==128, h=1)
// Block: 32 edges x 128 outputs, 256 threads; thread tile 4 edges x 4 outputs.
__global__ void __launch_bounds__(256) k_main(
    const float* __restrict__ x,
    const float* __restrict__ w2,
    const float* __restrict__ b2) {
    __shared__ float s_xj[32 * 132];
    __shared__ float s_h [32 * 132];
    __shared__ float s_w [16 * 128];
    __shared__ int   s_src[32];

    const int tid = threadIdx.x;
    const int e0  = blockIdx.x * 32;
    const int og  = tid & 31;
    const int eg  = (tid >> 5) * 4;

    if (tid < 32) s_src[tid] = g_src[e0 + tid];
    __syncthreads();

    for (int idx = tid; idx < 32 * D; idx += 256) {
        const int e = idx >> 7, c = idx & 127;
        s_xj[e * 132 + c] = x[(size_t)s_src[e] * D + c];
        s_h [e * 132 + c] = g_h[(size_t)(e0 + e) * D + c];
    }
    __syncthreads();

    float acc[4][4];
#pragma unroll
    for (int e = 0; e < 4; e++)
#pragma unroll
        for (int p = 0; p < 4; p++) acc[e][p] = 0.0f;

    for (int k = 0; k < 129; k++) {
        const float* wrow = (k < 128) ? (w2 + (size_t)k * (D * D)) : b2;
        float hk[4];
#pragma unroll
        for (int e = 0; e < 4; e++)
            hk[e] = (k < 128) ? s_h[(eg + e) * 132 + k] : 1.0f;

        for (int i0 = 0; i0 < 128; i0 += 16) {
            __syncthreads();
            const float4* gsrc = (const float4*)(wrow + (size_t)i0 * D);
            ((float4*)s_w)[tid]       = gsrc[tid];
            ((float4*)s_w)[tid + 256] = gsrc[tid + 256];
            __syncthreads();

#pragma unroll
            for (int j = 0; j < 16; j++) {
                float xv[4];
#pragma unroll
                for (int e = 0; e < 4; e++)
                    xv[e] = hk[e] * s_xj[(eg + e) * 132 + i0 + j];
                const float* wr = s_w + j * 128 + og;
                const float w0  = wr[0];
                const float w1v = wr[32];
                const float w2v = wr[64];
                const float w3v = wr[96];
#pragma unroll
                for (int e = 0; e < 4; e++) {
                    acc[e][0] += xv[e] * w0;
                    acc[e][1] += xv[e] * w1v;
                    acc[e][2] += xv[e] * w2v;
                    acc[e][3] += xv[e] * w3v;
                }
            }
        }
    }

#pragma unroll
    for (int e = 0; e < 4; e++) {
        const int ge  = e0 + eg + e;
        const int dst = g_dst[ge];
        float* srow = g_sum + (size_t)dst * D;
#pragma unroll
        for (int p = 0; p < 4; p++)
            atomicAdd(srow + og + p * 32, acc[e][p]);
        if (og == 0) atomicAdd(&g_cnt[dst], 1.0f);
    }
}

// ---------------- kernel 3: out = x + gelu(mean + x@root + bias) -----------
__global__ void __launch_bounds__(128) k_out(
        const float* __restrict__ x,
        const float* __restrict__ root,
        const float* __restrict__ bias,
        float*       __restrict__ out) {
    __shared__ float s[32 * D];
    const int n0 = blockIdx.x * 32;
    const int c  = threadIdx.x;
    const int nrows = (NN - n0) < 32 ? (NN - n0) : 32;

    for (int idx = c; idx < nrows * D; idx += 128)
        s[idx] = x[(size_t)n0 * D + idx];
    __syncthreads();

    float acc[32];
    const float bc = bias[c];
#pragma unroll
    for (int e = 0; e < 32; e++) acc[e] = bc;

    for (int k = 0; k < D; k++) {
        const float w = root[k * D + c];
#pragma unroll
        for (int e = 0; e < 32; e++) acc[e] += s[e * D + k] * w;
    }

    for (int e = 0; e < nrows; e++) {
        const int n = n0 + e;
        const float cn   = g_cnt[n];
        const float aggr = g_sum[(size_t)n * D + c] / fmaxf(cn, 1.0f);
        const float v = aggr + acc[e];
        const float g = 0.5f * v * (1.0f + erff(v * 0.7071067811865476f));
        out[(size_t)n * D + c] = s[e * D + c] + g;
    }
}

// ---------------- launch ----------------------------------------------------
extern "C" void kernel_launch(void* const* d_in, const int* in_sizes, int n_in,
                              void* d_out, int out_size) {
    const float* x    = (const float*)d_in[0];
    const void*  eidx = d_in[1];
    const float* ea   = (const float*)d_in[2];
    const float* w1   = (const float*)d_in[3];
    const float* b1   = (const float*)d_in[4];
    const float* w2   = (const float*)d_in[5];
    const float* b2   = (const float*)d_in[6];
    const float* root = (const float*)d_in[7];
    const float* bias = (const float*)d_in[8];
    float*       out  = (float*)d_out;

    k_detect<<<1, 256>>>((const unsigned*)eidx);
    k_convert<<<(E_EDGES + 255) / 256, 256>>>(eidx);
    k_zero<<<(NN * D + 255) / 256, 256>>>();
    k_edge_mlp1<<<E_EDGES / 32, 128>>>(ea, w1, b1);
    k_main<<<E_EDGES / 32, 256>>>(x, w2, b2);
    k_out<<<(NN + 31) / 32, 128>>>(x, root, bias, out);
}

// round 5
// speedup vs baseline: 5.7244x; 5.7244x over previous
#include <cuda_runtime.h>
#include <cstdint>

#define E_EDGES 16384
#define NN      10000
#define D       128
#define NCHUNK  258                   // 129 k-slices x 2 i-halves
#define CH_FLOATS 9216                // 8 ib * 32 lanes * 36 floats (32 + 4 pad)
#define CH_BYTES  (CH_FLOATS * 4)     // 36864

// ---------------- scratch (device globals; no allocation allowed) ----------
__device__ float g_h[E_EDGES * D];
__device__ float g_sum[NN * D];
__device__ float g_cnt[NN];
__device__ int   g_src[E_EDGES];
__device__ int   g_dst[E_EDGES];
__device__ int   g_is64;
__device__ __align__(128) float g_w2t[NCHUNK * CH_FLOATS];   // fragment-packed w2^T (+b2), tf32

// ---------------- helpers ----------------------------------------------------
static __device__ __forceinline__ unsigned smem_u32(const void* p) {
    unsigned a;
    asm("{ .reg .u64 t; cvta.to.shared.u64 t, %1; cvt.u32.u64 %0, t; }"
        : "=r"(a) : "l"(p));
    return a;
}
static __device__ __forceinline__ unsigned f2tf32(float f) {
    unsigned r;
    asm("cvt.rna.tf32.f32 %0, %1;" : "=r"(r) : "f"(f));
    return r;
}
static __device__ __forceinline__ void mma_tf32(float* d,
        unsigned a0, unsigned a1, unsigned a2, unsigned a3,
        unsigned b0, unsigned b1) {
    asm volatile(
        "mma.sync.aligned.m16n8k8.row.col.f32.tf32.tf32.f32 "
        "{%0,%1,%2,%3}, {%4,%5,%6,%7}, {%8,%9}, {%0,%1,%2,%3};"
        : "+f"(d[0]), "+f"(d[1]), "+f"(d[2]), "+f"(d[3])
        : "r"(a0), "r"(a1), "r"(a2), "r"(a3), "r"(b0), "r"(b1));
}
static __device__ __forceinline__ void cp16(unsigned sdst, const void* gsrc) {
    asm volatile("cp.async.cg.shared.global [%0], [%1], 16;"
                 :: "r"(sdst), "l"(gsrc) : "memory");
}
#define CP_COMMIT() asm volatile("cp.async.commit_group;" ::: "memory")
#define CP_WAIT1()  asm volatile("cp.async.wait_group 1;" ::: "memory")

// ---------------- dtype detect / canonicalize -------------------------------
__global__ void __launch_bounds__(256) k_detect(const unsigned* __restrict__ a) {
    __shared__ unsigned red[256];
    unsigned acc = 0;
    for (int i = threadIdx.x; i < E_EDGES; i += 256) acc |= a[2 * i + 1];
    red[threadIdx.x] = acc;
    __syncthreads();
    for (int s = 128; s > 0; s >>= 1) {
        if (threadIdx.x < s) red[threadIdx.x] |= red[threadIdx.x + s];
        __syncthreads();
    }
    if (threadIdx.x == 0) g_is64 = (red[0] == 0) ? 1 : 0;
}
__global__ void __launch_bounds__(256) k_convert(const void* __restrict__ ebuf) {
    const int i = blockIdx.x * blockDim.x + threadIdx.x;
    if (i >= E_EDGES) return;
    int s, d;
    if (g_is64) {
        const long long* a = (const long long*)ebuf;
        s = (int)a[i]; d = (int)a[E_EDGES + i];
    } else {
        const int* a = (const int*)ebuf;
        s = a[i]; d = a[E_EDGES + i];
    }
    g_src[i] = min(max(s, 0), NN - 1);
    g_dst[i] = min(max(d, 0), NN - 1);
}

// ---------------- zero scratch ----------------------------------------------
__global__ void k_zero() {
    int i = blockIdx.x * blockDim.x + threadIdx.x;
    if (i < NN * D) g_sum[i] = 0.0f;
    if (i < NN)     g_cnt[i] = 0.0f;
}

// ---------------- build fragment-packed w2^T (tf32) -------------------------
// chunk c = (k = c>>1, ih = c&1). Within chunk:
//   w = ib*1152 + l*36 + q ; q<32: p = q>>2, j = q&3
//   i = ih*64 + ib*8 + (l&3) + 4*(j&1)
//   o = 16*p + (l>>2) + 8*(j>>1)
//   value = tf32( src[i*128 + o] ),  src = w2 row k (or b2 for k==128)
__global__ void __launch_bounds__(256) k_build(
        const float* __restrict__ w2, const float* __restrict__ b2) {
    const int c = blockIdx.x, k = c >> 1, ih = c & 1;
    const float* src = (k < 128) ? (w2 + (size_t)k * (D * D)) : b2;
    float* out = g_w2t + (size_t)c * CH_FLOATS;
    for (int w = threadIdx.x; w < CH_FLOATS; w += 256) {
        const int ib = w / 1152;
        const int r  = w - ib * 1152;
        const int l  = r / 36;
        const int q  = r - l * 36;
        float v = 0.0f;
        if (q < 32) {
            const int p = q >> 2, j = q & 3;
            const int i = ih * 64 + ib * 8 + (l & 3) + 4 * (j & 1);
            const int o = 16 * p + (l >> 2) + 8 * (j >> 1);
            v = src[i * D + o];
        }
        out[w] = __uint_as_float(f2tf32(v));
    }
}

// ---------------- edge MLP1: h = relu(ea @ w1 + b1) --------------------------
// 256 threads, 32 edges/block. thread: cq = tid&31 -> cols 4cq..+3 ; er = tid>>5
// -> edges 4er..+3. Per k: 4 broadcast LDS + 1 float4 w1 row + 16 FFMA.
__global__ void __launch_bounds__(256) k_edge_mlp1(
        const float* __restrict__ ea, const float* __restrict__ w1,
        const float* __restrict__ b1) {
    __shared__ float s[32 * 132];
    const int e0 = blockIdx.x * 32;
    const int tid = threadIdx.x, cq = tid & 31, er = tid >> 5;
    for (int idx = tid; idx < 32 * 32; idx += 256) {
        const int e = idx >> 5, q = idx & 31;
        *(float4*)&s[e * 132 + 4 * q] =
            *(const float4*)&ea[(size_t)(e0 + e) * D + 4 * q];
    }
    __syncthreads();
    const float4 bq = *(const float4*)&b1[4 * cq];
    float acc[4][4];
#pragma unroll
    for (int e = 0; e < 4; e++) {
        acc[e][0] = bq.x; acc[e][1] = bq.y; acc[e][2] = bq.z; acc[e][3] = bq.w;
    }
    for (int k = 0; k < D; k++) {
        const float4 wq = *(const float4*)&w1[k * D + 4 * cq];
#pragma unroll
        for (int e = 0; e < 4; e++) {
            const float xv = s[(er * 4 + e) * 132 + k];
            acc[e][0] += xv * wq.x; acc[e][1] += xv * wq.y;
            acc[e][2] += xv * wq.z; acc[e][3] += xv * wq.w;
        }
    }
#pragma unroll
    for (int e = 0; e < 4; e++) {
        float4 o;
        o.x = fmaxf(acc[e][0], 0.0f); o.y = fmaxf(acc[e][1], 0.0f);
        o.z = fmaxf(acc[e][2], 0.0f); o.w = fmaxf(acc[e][3], 0.0f);
        *(float4*)&g_h[(size_t)(e0 + er * 4 + e) * D + 4 * cq] = o;
    }
}

// ---------------- main: tensor-core (mma.sync tf32) bilinear + scatter ------
// CTA: 128 edges, 8 warps. warp w: rows m0=16w; lane l: e0=m0+l/4, e1=e0+8.
// smem: s_src[128] | s_x[128x132] | s_h[128x132] | B double buffer 2x9216.
#define S_X   512
#define S_H   (S_X + 128 * 132 * 4)
#define S_B   (S_H + 128 * 132 * 4)
#define SMEM_SZ (S_B + 2 * CH_BYTES)
__global__ void __launch_bounds__(256) k_main(const float* __restrict__ x) {
    extern __shared__ char smem[];
    int*   s_src = (int*)smem;
    float* s_x   = (float*)(smem + S_X);
    float* s_h   = (float*)(smem + S_H);
    float* s_b   = (float*)(smem + S_B);
    const unsigned sb_b = smem_u32(s_b);

    const int tid = threadIdx.x, l = tid & 31, w = tid >> 5;
    const int eb = blockIdx.x * 128;
    const int m0 = w * 16;
    const int r0 = m0 + (l >> 2), r1 = r0 + 8, cl = l & 3;

    if (tid < 128) s_src[tid] = g_src[eb + tid];
    __syncthreads();

    // prologue B copies (chunks 0,1) — overlap with x/h staging
    {
        const float* src0 = g_w2t;
        const float* src1 = g_w2t + CH_FLOATS;
#pragma unroll
        for (int i = 0; i < 9; i++) {
            const int t = tid + 256 * i;
            cp16(sb_b + t * 16, src0 + t * 4);
        }
        CP_COMMIT();
#pragma unroll
        for (int i = 0; i < 9; i++) {
            const int t = tid + 256 * i;
            cp16(sb_b + CH_BYTES + t * 16, src1 + t * 4);
        }
        CP_COMMIT();
    }

    // stage x_j and h tiles (float4, coalesced)
    for (int idx = tid; idx < 128 * 32; idx += 256) {
        const int e = idx >> 5, q = idx & 31;
        *(float4*)&s_x[e * 132 + 4 * q] =
            *(const float4*)&x[(size_t)s_src[e] * D + 4 * q];
        *(float4*)&s_h[e * 132 + 4 * q] =
            *(const float4*)&g_h[(size_t)(eb + e) * D + 4 * q];
    }

    float acc[16][4];
#pragma unroll
    for (int nb = 0; nb < 16; nb++)
#pragma unroll
        for (int j = 0; j < 4; j++) acc[nb][j] = 0.0f;

    for (int j = 0; j < NCHUNK; j++) {
        CP_WAIT1();
        __syncthreads();          // buffer j&1 fully resident for all warps
        const int k = j >> 1, ih = j & 1;
        float h0 = 1.0f, h1 = 1.0f;
        if (k < 128) {
            h0 = s_h[r0 * 132 + k];
            h1 = s_h[r1 * 132 + k];
        }
        const float* bb = s_b + (j & 1) * CH_FLOATS;
#pragma unroll
        for (int ib = 0; ib < 8; ib++) {
            const int ibase = ih * 64 + ib * 8;
            const float x00 = s_x[r0 * 132 + ibase + cl];
            const float x01 = s_x[r0 * 132 + ibase + cl + 4];
            const float x10 = s_x[r1 * 132 + ibase + cl];
            const float x11 = s_x[r1 * 132 + ibase + cl + 4];
            const unsigned a0 = f2tf32(h0 * x00);
            const unsigned a2 = f2tf32(h0 * x01);
            const unsigned a1 = f2tf32(h1 * x10);
            const unsigned a3 = f2tf32(h1 * x11);
            const float4* bq = (const float4*)(bb + ib * 1152 + l * 36);
#pragma unroll
            for (int p = 0; p < 8; p++) {
                const float4 bv = bq[p];
                mma_tf32(acc[2 * p],     a0, a1, a2, a3,
                         __float_as_uint(bv.x), __float_as_uint(bv.y));
                mma_tf32(acc[2 * p + 1], a0, a1, a2, a3,
                         __float_as_uint(bv.z), __float_as_uint(bv.w));
            }
        }
        __syncthreads();          // everyone done reading buffer j&1
        if (j + 2 < NCHUNK) {
            const float* src = g_w2t + (size_t)(j + 2) * CH_FLOATS;
            const unsigned dst = sb_b + (j & 1) * CH_BYTES;
#pragma unroll
            for (int i = 0; i < 9; i++) {
                const int t = tid + 256 * i;
                cp16(dst + t * 16, src + t * 4);
            }
        }
        CP_COMMIT();
    }

    // scatter-add: lane holds rows r0 (d0,d1) and r1 (d2,d3) per n-block
    const int ge0 = eb + r0, ge1 = eb + r1;
    const int d0 = g_dst[ge0], d1 = g_dst[ge1];
    float* row0 = g_sum + (size_t)d0 * D;
    float* row1 = g_sum + (size_t)d1 * D;
#pragma unroll
    for (int nb = 0; nb < 16; nb++) {
        const int c = nb * 8 + 2 * cl;
        atomicAdd(row0 + c,     acc[nb][0]);
        atomicAdd(row0 + c + 1, acc[nb][1]);
        atomicAdd(row1 + c,     acc[nb][2]);
        atomicAdd(row1 + c + 1, acc[nb][3]);
    }
    if (cl == 0) {
        atomicAdd(&g_cnt[d0], 1.0f);
        atomicAdd(&g_cnt[d1], 1.0f);
    }
}

// ---------------- out = x + gelu(mean + x@root + bias) ----------------------
__global__ void __launch_bounds__(256) k_out(
        const float* __restrict__ x, const float* __restrict__ root,
        const float* __restrict__ bias, float* __restrict__ out) {
    __shared__ float s[32 * 132];
    const int n0 = blockIdx.x * 32;
    const int tid = threadIdx.x, cq = tid & 31, er = tid >> 5;
    for (int idx = tid; idx < 32 * 32; idx += 256) {
        const int e = idx >> 5, q = idx & 31;
        const int n = n0 + e;
        float4 v = make_float4(0.f, 0.f, 0.f, 0.f);
        if (n < NN) v = *(const float4*)&x[(size_t)n * D + 4 * q];
        *(float4*)&s[e * 132 + 4 * q] = v;
    }
    __syncthreads();
    const float4 bq = *(const float4*)&bias[4 * cq];
    float acc[4][4];
#pragma unroll
    for (int e = 0; e < 4; e++) {
        acc[e][0] = bq.x; acc[e][1] = bq.y; acc[e][2] = bq.z; acc[e][3] = bq.w;
    }
    for (int k = 0; k < D; k++) {
        const float4 wq = *(const float4*)&root[k * D + 4 * cq];
#pragma unroll
        for (int e = 0; e < 4; e++) {
            const float xv = s[(er * 4 + e) * 132 + k];
            acc[e][0] += xv * wq.x; acc[e][1] += xv * wq.y;
            acc[e][2] += xv * wq.z; acc[e][3] += xv * wq.w;
        }
    }
#pragma unroll
    for (int e = 0; e < 4; e++) {
        const int n = n0 + er * 4 + e;
        if (n >= NN) continue;
        const float cn = fmaxf(g_cnt[n], 1.0f);
        const float4 sg = *(const float4*)&g_sum[(size_t)n * D + 4 * cq];
        float v0 = sg.x / cn + acc[e][0];
        float v1 = sg.y / cn + acc[e][1];
        float v2 = sg.z / cn + acc[e][2];
        float v3 = sg.w / cn + acc[e][3];
        const float kk = 0.7071067811865476f;
        float4 o;
        o.x = s[(er * 4 + e) * 132 + 4 * cq + 0] + 0.5f * v0 * (1.0f + erff(v0 * kk));
        o.y = s[(er * 4 + e) * 132 + 4 * cq + 1] + 0.5f * v1 * (1.0f + erff(v1 * kk));
        o.z = s[(er * 4 + e) * 132 + 4 * cq + 2] + 0.5f * v2 * (1.0f + erff(v2 * kk));
        o.w = s[(er * 4 + e) * 132 + 4 * cq + 3] + 0.5f * v3 * (1.0f + erff(v3 * kk));
        *(float4*)&out[(size_t)n * D + 4 * cq] = o;
    }
}

// ---------------- launch -----------------------------------------------------
extern "C" void kernel_launch(void* const* d_in, const int* in_sizes, int n_in,
                              void* d_out, int out_size) {
    const float* x    = (const float*)d_in[0];
    const void*  eidx = d_in[1];
    const float* ea   = (const float*)d_in[2];
    const float* w1   = (const float*)d_in[3];
    const float* b1   = (const float*)d_in[4];
    const float* w2   = (const float*)d_in[5];
    const float* b2   = (const float*)d_in[6];
    const float* root = (const float*)d_in[7];
    const float* bias = (const float*)d_in[8];
    float*       out  = (float*)d_out;

    cudaFuncSetAttribute(k_main, cudaFuncAttributeMaxDynamicSharedMemorySize,
                         SMEM_SZ);

    k_detect<<<1, 256>>>((const unsigned*)eidx);
    k_convert<<<(E_EDGES + 255) / 256, 256>>>(eidx);
    k_zero<<<(NN * D + 255) / 256, 256>>>();
    k_build<<<NCHUNK, 256>>>(w2, b2);
    k_edge_mlp1<<<E_EDGES / 32, 256>>>(ea, w1, b1);
    k_main<<<E_EDGES / 128, 256, SMEM_SZ>>>(x);
    k_out<<<(NN + 31) / 32, 256>>>(x, root, bias, out);
}